// round 1
// baseline (speedup 1.0000x reference)
#include <cuda_runtime.h>
#include <cuda_bf16.h>
#include <math.h>

#define CROP 448
#define NR   56      // cells per side
#define NB   55      // blocks per side
#define B    48
#define IMG  512
#define TOP  32

// Cell histogram scratch: [b][cell_r][cell_c][bin]
__device__ float g_hist[(size_t)B * NR * NR * 9];

// ---------------------------------------------------------------------------
// Kernel 1: gray -> sqrt -> gradients -> per-cell 9-bin histograms
// grid: (NR, B), block: 448 threads (one per crop column)
// ---------------------------------------------------------------------------
__global__ __launch_bounds__(CROP) void hog_cells_kernel(
    const float* __restrict__ x, const float* __restrict__ coeffs,
    float* __restrict__ hist)
{
    __shared__ float sg[10][CROP];   // sqrt(gray) rows [r0-1, r0+8]

    const int cr = blockIdx.x;       // cell row 0..55
    const int b  = blockIdx.y;
    const int c  = threadIdx.x;      // crop column 0..447
    const int r0 = cr * 8;

    const float c0 = coeffs[0], c1 = coeffs[1], c2 = coeffs[2];
    const float* base = x + (size_t)b * 3 * IMG * IMG;

    // Load 10 rows of sqrt(gray) into smem (rows clamped; boundary rows unused
    // because g_row is forced to 0 there).
    #pragma unroll
    for (int i = 0; i < 10; i++) {
        int r = r0 - 1 + i;
        r = min(max(r, 0), CROP - 1);
        size_t off = (size_t)(r + TOP) * IMG + TOP + c;
        float v = c0 * base[off]
                + c1 * base[off + (size_t)IMG * IMG]
                + c2 * base[off + (size_t)2 * IMG * IMG];
        sg[i][c] = sqrtf(v);
    }
    __syncthreads();

    float h[9];
    #pragma unroll
    for (int k = 0; k < 9; k++) h[k] = 0.f;

    #pragma unroll
    for (int i = 0; i < 8; i++) {
        int r = r0 + i;  // crop row
        float gr = 0.f, gc = 0.f;
        if (r > 0 && r < CROP - 1) gr = sg[i + 2][c] - sg[i][c];
        if (c > 0 && c < CROP - 1) gc = sg[i + 1][c + 1] - sg[i + 1][c - 1];

        float mag = sqrtf(gr * gr + gc * gc) * (1.0f / 64.0f);
        float ang = atan2f(gr, gc) * 57.29577951308232f;   // degrees
        if (ang < 0.f)     ang += 180.f;
        if (ang >= 180.f)  ang -= 180.f;                    // deg==180 -> 0
        int bin = (int)floorf(ang * (1.0f / 20.0f));
        bin = min(max(bin, 0), 8);

        #pragma unroll
        for (int k = 0; k < 9; k++)
            h[k] += (k == bin) ? mag : 0.f;
    }

    // Reduce over the 8 columns of each cell (8 consecutive lanes in a warp).
    #pragma unroll
    for (int k = 0; k < 9; k++) {
        h[k] += __shfl_xor_sync(0xffffffffu, h[k], 1);
        h[k] += __shfl_xor_sync(0xffffffffu, h[k], 2);
        h[k] += __shfl_xor_sync(0xffffffffu, h[k], 4);
    }

    if ((c & 7) == 0) {
        int cell = c >> 3;   // 0..55
        size_t o = (((size_t)b * NR + cr) * NR + cell) * 9;
        #pragma unroll
        for (int k = 0; k < 9; k++) hist[o + k] = h[k];
    }
}

// ---------------------------------------------------------------------------
// Kernel 2: 2x2-cell blocks, L2-Hys normalization, write output
// one thread per (b, I, J) block descriptor
// ---------------------------------------------------------------------------
__global__ void hog_blocks_kernel(const float* __restrict__ hist,
                                  float* __restrict__ out)
{
    int idx = blockIdx.x * blockDim.x + threadIdx.x;
    const int total = B * NB * NB;
    if (idx >= total) return;

    int J = idx % NB;
    int t = idx / NB;
    int I = t % NB;
    int b = t / NB;

    const float* hb = hist + (((size_t)b * NR + I) * NR + J) * 9;
    // cell order: (I,J), (I,J+1), (I+1,J), (I+1,J+1)
    const float* cp[4] = { hb, hb + 9, hb + NR * 9, hb + NR * 9 + 9 };

    float v[36];
    float ss = 0.f;
    #pragma unroll
    for (int g = 0; g < 4; g++) {
        #pragma unroll
        for (int k = 0; k < 9; k++) {
            float f = cp[g][k];
            v[g * 9 + k] = f;
            ss += f * f;
        }
    }

    float inv1 = rsqrtf(ss + 1e-10f);   // sqrt(ss + EPS^2)
    float ss2 = 0.f;
    #pragma unroll
    for (int k = 0; k < 36; k++) {
        float f = fminf(v[k] * inv1, 0.2f);
        v[k] = f;
        ss2 += f * f;
    }
    float inv2 = rsqrtf(ss2 + 1e-10f);

    float* o = out + (size_t)idx * 36;
    #pragma unroll
    for (int k = 0; k < 36; k++) o[k] = v[k] * inv2;
}

// ---------------------------------------------------------------------------
extern "C" void kernel_launch(void* const* d_in, const int* in_sizes, int n_in,
                              void* d_out, int out_size)
{
    const float* x      = (const float*)d_in[0];
    const float* coeffs = (const float*)d_in[1];
    float* out          = (float*)d_out;

    float* hist;
    cudaGetSymbolAddress((void**)&hist, g_hist);

    dim3 g1(NR, B);
    hog_cells_kernel<<<g1, CROP>>>(x, coeffs, hist);

    const int total = B * NB * NB;
    hog_blocks_kernel<<<(total + 127) / 128, 128>>>(hist, out);
}

// round 2
// speedup vs baseline: 1.1999x; 1.1999x over previous
#include <cuda_runtime.h>
#include <cuda_bf16.h>
#include <math.h>

#define CROP 448
#define NR   56      // cells per side
#define NB   55      // blocks per side
#define B    48
#define IMG  512
#define TOP  32

// Cell histogram scratch: [b][cell_r][cell_c][bin]
__device__ float g_hist[(size_t)B * NR * NR * 9];

// ---------------------------------------------------------------------------
// Kernel 1: gray -> sqrt -> gradients -> per-cell 9-bin histograms
// grid: (NR, B), block: 448 threads (one per crop column)
// ---------------------------------------------------------------------------
__global__ __launch_bounds__(CROP) void hog_cells_kernel(
    const float* __restrict__ x, const float* __restrict__ coeffs,
    float* __restrict__ hist)
{
    __shared__ float sg[10][CROP];   // sqrt(gray) rows [r0-1, r0+8]

    const int cr = blockIdx.x;       // cell row 0..55
    const int b  = blockIdx.y;
    const int c  = threadIdx.x;      // crop column 0..447
    const int r0 = cr * 8;

    const float c0 = coeffs[0], c1 = coeffs[1], c2 = coeffs[2];
    const float* base = x + (size_t)b * 3 * IMG * IMG;

    #pragma unroll
    for (int i = 0; i < 10; i++) {
        int r = r0 - 1 + i;
        r = min(max(r, 0), CROP - 1);
        size_t off = (size_t)(r + TOP) * IMG + TOP + c;
        float v = c0 * base[off]
                + c1 * base[off + (size_t)IMG * IMG]
                + c2 * base[off + (size_t)2 * IMG * IMG];
        sg[i][c] = sqrtf(v);
    }
    __syncthreads();

    // sin/cos of k*20 degrees, k=1..8
    const float SN[8] = {0.342020143f, 0.642787610f, 0.866025404f, 0.984807753f,
                         0.984807753f, 0.866025404f, 0.642787610f, 0.342020143f};
    const float CS[8] = {0.939692621f, 0.766044443f, 0.500000000f, 0.173648178f,
                        -0.173648178f,-0.500000000f,-0.766044443f,-0.939692621f};

    float h[9];
    #pragma unroll
    for (int k = 0; k < 9; k++) h[k] = 0.f;

    #pragma unroll
    for (int i = 0; i < 8; i++) {
        int r = r0 + i;  // crop row
        float gr = 0.f, gc = 0.f;
        if (r > 0 && r < CROP - 1) gr = sg[i + 2][c] - sg[i][c];
        if (c > 0 && c < CROP - 1) gc = sg[i + 1][c + 1] - sg[i + 1][c - 1];

        float mag = sqrtf(gr * gr + gc * gc) * (1.0f / 64.0f);

        // Fold direction into the upper half-plane: angle(u,v) in [0,180).
        float u = gc, v = gr;
        if (gr < 0.f || (gr == 0.f && gc < 0.f)) { u = -u; v = -v; }

        // bin = number of boundary angles 20k (k=1..8) that angle(u,v) passes
        int bin = 0;
        #pragma unroll
        for (int k = 0; k < 8; k++)
            bin += (CS[k] * v - SN[k] * u >= 0.f) ? 1 : 0;

        #pragma unroll
        for (int k = 0; k < 9; k++)
            h[k] += (k == bin) ? mag : 0.f;
    }

    // Reduce over the 8 columns of each cell (8 consecutive lanes in a warp).
    #pragma unroll
    for (int k = 0; k < 9; k++) {
        h[k] += __shfl_xor_sync(0xffffffffu, h[k], 1);
        h[k] += __shfl_xor_sync(0xffffffffu, h[k], 2);
        h[k] += __shfl_xor_sync(0xffffffffu, h[k], 4);
    }

    if ((c & 7) == 0) {
        int cell = c >> 3;   // 0..55
        size_t o = (((size_t)b * NR + cr) * NR + cell) * 9;
        #pragma unroll
        for (int k = 0; k < 9; k++) hist[o + k] = h[k];
    }
}

// ---------------------------------------------------------------------------
// Kernel 2: L2-Hys block normalization.
// One CTA per (b, I) block-row: loads 2 contiguous hist rows (1008 floats),
// computes 55 block descriptors, writes 1980 contiguous floats coalesced.
// ---------------------------------------------------------------------------
#define K2_THREADS 512

__global__ __launch_bounds__(K2_THREADS) void hog_blocks_kernel(
    const float* __restrict__ hist, float* __restrict__ out)
{
    __shared__ float sh[2 * NR * 9];    // hist rows I, I+1 (1008)
    __shared__ float vbuf[NB * 36];     // clipped values (1980)
    __shared__ float cellss[NR];        // per-cell (pair) sum of squares
    __shared__ float inv1[NB];
    __shared__ float inv2[NB];

    const int b = blockIdx.x / NB;
    const int I = blockIdx.x % NB;
    const int tid = threadIdx.x;

    const float* src = hist + ((size_t)b * NR + I) * NR * 9;
    #pragma unroll
    for (int e = tid; e < 2 * NR * 9; e += K2_THREADS) sh[e] = src[e];
    __syncthreads();

    if (tid < NR) {
        float s = 0.f;
        #pragma unroll
        for (int k = 0; k < 9; k++) {
            float a = sh[tid * 9 + k];
            float d = sh[NR * 9 + tid * 9 + k];
            s += a * a + d * d;
        }
        cellss[tid] = s;
    }
    __syncthreads();

    if (tid < NB)
        inv1[tid] = rsqrtf(cellss[tid] + cellss[tid + 1] + 1e-10f);
    __syncthreads();

    for (int e = tid; e < NB * 36; e += K2_THREADS) {
        int J = e / 36;
        int k = e - J * 36;
        int g = k / 9;
        int bin = k - g * 9;
        float v = sh[(g >> 1) * (NR * 9) + (J + (g & 1)) * 9 + bin];
        vbuf[e] = fminf(v * inv1[J], 0.2f);
    }
    __syncthreads();

    if (tid < NB) {
        float s = 0.f;
        #pragma unroll
        for (int k = 0; k < 36; k++) {
            float f = vbuf[tid * 36 + k];
            s += f * f;
        }
        inv2[tid] = rsqrtf(s + 1e-10f);
    }
    __syncthreads();

    float* o = out + (size_t)blockIdx.x * (NB * 36);
    for (int e = tid; e < NB * 36; e += K2_THREADS)
        o[e] = vbuf[e] * inv2[e / 36];
}

// ---------------------------------------------------------------------------
extern "C" void kernel_launch(void* const* d_in, const int* in_sizes, int n_in,
                              void* d_out, int out_size)
{
    const float* x      = (const float*)d_in[0];
    const float* coeffs = (const float*)d_in[1];
    float* out          = (float*)d_out;

    float* hist;
    cudaGetSymbolAddress((void**)&hist, g_hist);

    dim3 g1(NR, B);
    hog_cells_kernel<<<g1, CROP>>>(x, coeffs, hist);

    hog_blocks_kernel<<<B * NB, K2_THREADS>>>(hist, out);
}